// round 6
// baseline (speedup 1.0000x reference)
#include <cuda_runtime.h>
#include <math.h>

#define NEGF (-1e9f)
#define PADW 68

// ---------- scratch (device globals; allocation is forbidden) ----------
__device__ float    g_x [4194304];   // [B*TX, 256]
__device__ float    g_q [4194304];
__device__ float    g_k [4194304];
__device__ float    g_v [4194304];
__device__ float    g_o [4194304];
__device__ float    g_t [4194304];
__device__ float    g_s [16777216];  // [B*H*TX, TX]
__device__ float    g_h [16777216];  // [B*TX, 1024]
__device__ float    g_vt[16777216];  // [B, TY, TX]
__device__ float    g_w1t[9437184];  // [L,9,256,1024]
__device__ float    g_w2t[9437184];  // [L,9,1024,256]
__device__ unsigned g_dir[524288];   // [B,TY,16]
__device__ int      g_idx[32768];    // [B,TY]

// ---------- 16-step micro GEMM ----------
__device__ __forceinline__ void mm16(const float (*As)[PADW], const float (*Bs)[PADW],
                                     int tx, int ty, float acc[4][4]) {
#pragma unroll
    for (int k = 0; k < 16; ++k) {
        float4 a4 = *(const float4*)&As[k][ty * 4];
        float4 b4 = *(const float4*)&Bs[k][tx * 4];
        float a[4] = {a4.x, a4.y, a4.z, a4.w};
        float b[4] = {b4.x, b4.y, b4.z, b4.w};
#pragma unroll
        for (int i = 0; i < 4; ++i)
#pragma unroll
            for (int j = 0; j < 4; ++j)
                acc[i][j] = fmaf(a[i], b[j], acc[i][j]);
    }
}

// ---------- embedding + pos enc ----------
__global__ void k_embed(const int* __restrict__ tok, const float* __restrict__ emb,
                        const float* __restrict__ pos, float* __restrict__ x) {
    int row = blockIdx.x;          // b*512 + t
    int d = threadIdx.x;
    int t = row & 511;
    int id = tok[row];
    x[(size_t)row * 256 + d] = emb[(size_t)id * 256 + d] + pos[(size_t)t * 256 + d];
}

// ---------- C[16384,256] = A[16384,256] @ W[256,256] + bias ----------
__global__ void k_gemm_bias(const float* __restrict__ A, const float* __restrict__ W,
                            const float* __restrict__ bias, float* __restrict__ C) {
    __shared__ __align__(16) float As[16][PADW];
    __shared__ __align__(16) float Bs[16][PADW];
    int tid = threadIdx.x, tx = tid & 15, ty = tid >> 4;
    int n0 = blockIdx.x * 64, m0 = blockIdx.y * 64;
    int am = tid >> 2, ak = (tid & 3) * 4;
    int bk = tid >> 4, bn = (tid & 15) * 4;
    float acc[4][4] = {};
    for (int k0 = 0; k0 < 256; k0 += 16) {
        float4 av = *(const float4*)&A[(size_t)(m0 + am) * 256 + k0 + ak];
        As[ak + 0][am] = av.x; As[ak + 1][am] = av.y; As[ak + 2][am] = av.z; As[ak + 3][am] = av.w;
        *(float4*)&Bs[bk][bn] = *(const float4*)&W[(size_t)(k0 + bk) * 256 + n0 + bn];
        __syncthreads();
        mm16(As, Bs, tx, ty, acc);
        __syncthreads();
    }
    float4 b4 = *(const float4*)&bias[n0 + tx * 4];
    float bb[4] = {b4.x, b4.y, b4.z, b4.w};
#pragma unroll
    for (int i = 0; i < 4; ++i) {
        float4 r;
        r.x = acc[i][0] + bb[0]; r.y = acc[i][1] + bb[1];
        r.z = acc[i][2] + bb[2]; r.w = acc[i][3] + bb[3];
        *(float4*)&C[(size_t)(m0 + ty * 4 + i) * 256 + n0 + tx * 4] = r;
    }
}

// ---------- attention scores S[bh,q,k] = scale*Q.K + key-pad mask ----------
__global__ void k_scores(const float* __restrict__ Q, const float* __restrict__ K,
                         float* __restrict__ S, const int* __restrict__ srcL) {
    __shared__ __align__(16) float As[16][PADW];
    __shared__ __align__(16) float Bs[16][PADW];
    int tid = threadIdx.x, tx = tid & 15, ty = tid >> 4;
    int n0 = blockIdx.x * 64, m0 = blockIdx.y * 64, bh = blockIdx.z;
    int b = bh >> 1, h = bh & 1;
    const float* qb = Q + (size_t)b * 512 * 256 + h * 128;
    const float* kb = K + (size_t)b * 512 * 256 + h * 128;
    int am = tid >> 2, ak = (tid & 3) * 4;
    float acc[4][4] = {};
    for (int k0 = 0; k0 < 128; k0 += 16) {
        float4 av = *(const float4*)&qb[(size_t)(m0 + am) * 256 + k0 + ak];
        As[ak + 0][am] = av.x; As[ak + 1][am] = av.y; As[ak + 2][am] = av.z; As[ak + 3][am] = av.w;
        float4 bv = *(const float4*)&kb[(size_t)(n0 + am) * 256 + k0 + ak];
        Bs[ak + 0][am] = bv.x; Bs[ak + 1][am] = bv.y; Bs[ak + 2][am] = bv.z; Bs[ak + 3][am] = bv.w;
        __syncthreads();
        mm16(As, Bs, tx, ty, acc);
        __syncthreads();
    }
    int sl = srcL[b];
    const float scale = 0.08838834764831845f;  // 1/sqrt(128)
    int n = n0 + tx * 4;
#pragma unroll
    for (int i = 0; i < 4; ++i) {
        float4 r;
        r.x = (n + 0 >= sl) ? NEGF : acc[i][0] * scale;
        r.y = (n + 1 >= sl) ? NEGF : acc[i][1] * scale;
        r.z = (n + 2 >= sl) ? NEGF : acc[i][2] * scale;
        r.w = (n + 3 >= sl) ? NEGF : acc[i][3] * scale;
        *(float4*)&S[((size_t)bh * 512 + m0 + ty * 4 + i) * 512 + n] = r;
    }
}

// ---------- softmax over 512 (one block of 128 per row) ----------
__global__ void k_softmax(float* __restrict__ S) {
    __shared__ float red[4];
    size_t row = blockIdx.x;
    float4 v = ((float4*)(S + row * 512))[threadIdx.x];
    int lane = threadIdx.x & 31, wid = threadIdx.x >> 5;
    float m = fmaxf(fmaxf(v.x, v.y), fmaxf(v.z, v.w));
#pragma unroll
    for (int o = 16; o > 0; o >>= 1) m = fmaxf(m, __shfl_xor_sync(~0u, m, o));
    if (lane == 0) red[wid] = m;
    __syncthreads();
    m = fmaxf(fmaxf(red[0], red[1]), fmaxf(red[2], red[3]));
    __syncthreads();
    v.x = expf(v.x - m); v.y = expf(v.y - m); v.z = expf(v.z - m); v.w = expf(v.w - m);
    float s = v.x + v.y + v.z + v.w;
#pragma unroll
    for (int o = 16; o > 0; o >>= 1) s += __shfl_xor_sync(~0u, s, o);
    if (lane == 0) red[wid] = s;
    __syncthreads();
    s = red[0] + red[1] + red[2] + red[3];
    float inv = 1.0f / s;
    v.x *= inv; v.y *= inv; v.z *= inv; v.w *= inv;
    ((float4*)(S + row * 512))[threadIdx.x] = v;
}

// ---------- attn out: O[b,q,h*128+d] = sum_k S[bh,q,k] V[b,k,h*128+d] ----------
__global__ void k_attnout(const float* __restrict__ S, const float* __restrict__ V,
                          float* __restrict__ O) {
    __shared__ __align__(16) float As[16][PADW];
    __shared__ __align__(16) float Bs[16][PADW];
    int tid = threadIdx.x, tx = tid & 15, ty = tid >> 4;
    int n0 = blockIdx.x * 64, m0 = blockIdx.y * 64, bh = blockIdx.z;
    int b = bh >> 1, h = bh & 1;
    const float* sb = S + (size_t)bh * 512 * 512;
    const float* vb = V + (size_t)b * 512 * 256 + h * 128;
    int am = tid >> 2, ak = (tid & 3) * 4;
    int bk = tid >> 4, bn = (tid & 15) * 4;
    float acc[4][4] = {};
    for (int k0 = 0; k0 < 512; k0 += 16) {
        float4 av = *(const float4*)&sb[(size_t)(m0 + am) * 512 + k0 + ak];
        As[ak + 0][am] = av.x; As[ak + 1][am] = av.y; As[ak + 2][am] = av.z; As[ak + 3][am] = av.w;
        *(float4*)&Bs[bk][bn] = *(const float4*)&vb[(size_t)(k0 + bk) * 256 + n0 + bn];
        __syncthreads();
        mm16(As, Bs, tx, ty, acc);
        __syncthreads();
    }
#pragma unroll
    for (int i = 0; i < 4; ++i) {
        float4 r = {acc[i][0], acc[i][1], acc[i][2], acc[i][3]};
        *(float4*)&O[((size_t)b * 512 + m0 + ty * 4 + i) * 256 + h * 128 + n0 + tx * 4] = r;
    }
}

// ---------- layernorm(t + res)*g + b, zero pad rows ----------
__global__ void k_lnres(const float* __restrict__ t, const float* __restrict__ res,
                        const float* __restrict__ gam, const float* __restrict__ bet,
                        const int* __restrict__ srcL, float* __restrict__ out) {
    __shared__ float red[8];
    int row = blockIdx.x, d = threadIdx.x;
    size_t off = (size_t)row * 256 + d;
    float val = t[off] + res[off];
    float s = val;
#pragma unroll
    for (int o = 16; o > 0; o >>= 1) s += __shfl_xor_sync(~0u, s, o);
    if ((d & 31) == 0) red[d >> 5] = s;
    __syncthreads();
    float tot = 0.f;
#pragma unroll
    for (int i = 0; i < 8; ++i) tot += red[i];
    float mean = tot * (1.0f / 256.0f);
    float dv = val - mean;
    __syncthreads();
    float s2 = dv * dv;
#pragma unroll
    for (int o = 16; o > 0; o >>= 1) s2 += __shfl_xor_sync(~0u, s2, o);
    if ((d & 31) == 0) red[d >> 5] = s2;
    __syncthreads();
    float tot2 = 0.f;
#pragma unroll
    for (int i = 0; i < 8; ++i) tot2 += red[i];
    float o = dv * rsqrtf(tot2 * (1.0f / 256.0f) + 1e-5f) * gam[d] + bet[d];
    if ((row & 511) >= srcL[row >> 9]) o = 0.f;
    out[off] = o;
}

// ---------- conv1: H[m,f] = relu(sum_{dk,c} X[b,t+dk-4,c] * W1t[dk,c,f] + b1[f]) ----------
__global__ void k_conv1(const float* __restrict__ X, const float* __restrict__ Wt,
                        const float* __restrict__ bias, float* __restrict__ H) {
    __shared__ __align__(16) float As[16][PADW];
    __shared__ __align__(16) float Bs[16][PADW];
    int tid = threadIdx.x, tx = tid & 15, ty = tid >> 4;
    int n0 = blockIdx.x * 64, m0 = blockIdx.y * 64;
    int am = tid >> 2, ak = (tid & 3) * 4;
    int bk = tid >> 4, bn = (tid & 15) * 4;
    int bidx = m0 >> 9, tbase = m0 & 511;
    float acc[4][4] = {};
    for (int dk = 0; dk < 9; ++dk) {
        int tt = tbase + am + dk - 4;
        bool ok = ((unsigned)tt < 512u);
        const float* arow = X + ((size_t)(bidx << 9) + tt) * 256;
        const float* wrow = Wt + (size_t)dk * 256 * 1024;
        for (int k0 = 0; k0 < 256; k0 += 16) {
            float4 av = ok ? *(const float4*)&arow[k0 + ak] : make_float4(0.f, 0.f, 0.f, 0.f);
            As[ak + 0][am] = av.x; As[ak + 1][am] = av.y; As[ak + 2][am] = av.z; As[ak + 3][am] = av.w;
            *(float4*)&Bs[bk][bn] = *(const float4*)&wrow[(size_t)(k0 + bk) * 1024 + n0 + bn];
            __syncthreads();
            mm16(As, Bs, tx, ty, acc);
            __syncthreads();
        }
    }
    float4 b4 = *(const float4*)&bias[n0 + tx * 4];
    float bb[4] = {b4.x, b4.y, b4.z, b4.w};
#pragma unroll
    for (int i = 0; i < 4; ++i) {
        float4 r;
        r.x = fmaxf(acc[i][0] + bb[0], 0.f); r.y = fmaxf(acc[i][1] + bb[1], 0.f);
        r.z = fmaxf(acc[i][2] + bb[2], 0.f); r.w = fmaxf(acc[i][3] + bb[3], 0.f);
        *(float4*)&H[(size_t)(m0 + ty * 4 + i) * 1024 + n0 + tx * 4] = r;
    }
}

// ---------- conv2: T[m,d] = sum_{dk,f} H[b,t+dk-4,f] * W2t[dk,f,d] + b2[d] ----------
__global__ void k_conv2(const float* __restrict__ H, const float* __restrict__ Wt,
                        const float* __restrict__ bias, float* __restrict__ T) {
    __shared__ __align__(16) float As[16][PADW];
    __shared__ __align__(16) float Bs[16][PADW];
    int tid = threadIdx.x, tx = tid & 15, ty = tid >> 4;
    int n0 = blockIdx.x * 64, m0 = blockIdx.y * 64;
    int am = tid >> 2, ak = (tid & 3) * 4;
    int bk = tid >> 4, bn = (tid & 15) * 4;
    int bidx = m0 >> 9, tbase = m0 & 511;
    float acc[4][4] = {};
    for (int dk = 0; dk < 9; ++dk) {
        int tt = tbase + am + dk - 4;
        bool ok = ((unsigned)tt < 512u);
        const float* arow = H + ((size_t)(bidx << 9) + tt) * 1024;
        const float* wrow = Wt + (size_t)dk * 1024 * 256;
        for (int k0 = 0; k0 < 1024; k0 += 16) {
            float4 av = ok ? *(const float4*)&arow[k0 + ak] : make_float4(0.f, 0.f, 0.f, 0.f);
            As[ak + 0][am] = av.x; As[ak + 1][am] = av.y; As[ak + 2][am] = av.z; As[ak + 3][am] = av.w;
            *(float4*)&Bs[bk][bn] = *(const float4*)&wrow[(size_t)(k0 + bk) * 256 + n0 + bn];
            __syncthreads();
            mm16(As, Bs, tx, ty, acc);
            __syncthreads();
        }
    }
    float4 b4 = *(const float4*)&bias[n0 + tx * 4];
    float bb[4] = {b4.x, b4.y, b4.z, b4.w};
#pragma unroll
    for (int i = 0; i < 4; ++i) {
        float4 r;
        r.x = acc[i][0] + bb[0]; r.y = acc[i][1] + bb[1];
        r.z = acc[i][2] + bb[2]; r.w = acc[i][3] + bb[3];
        *(float4*)&T[(size_t)(m0 + ty * 4 + i) * 256 + n0 + tx * 4] = r;
    }
}

// ---------- weight transpose: src[L][R][C][9] -> dst[L][9][C][R] ----------
__global__ void k_wtrans(const float* __restrict__ src, float* __restrict__ dst, int R, int C) {
    __shared__ float s[32][33];
    int l = blockIdx.z;
    int CD = C * 9;
    int cd0 = blockIdx.x * 32, r0 = blockIdx.y * 32;
    const float* sp = src + (size_t)l * R * CD;
    float* dp = dst + (size_t)l * 9 * C * R;
    for (int i = threadIdx.y; i < 32; i += 8)
        s[i][threadIdx.x] = sp[(size_t)(r0 + i) * CD + cd0 + threadIdx.x];
    __syncthreads();
    for (int j = threadIdx.y; j < 32; j += 8) {
        int cd = cd0 + j;
        int c = cd / 9, dk = cd % 9;
        dp[((size_t)dk * C + c) * R + r0 + threadIdx.x] = s[threadIdx.x][j];
    }
}

// ---------- value transpose + mask: vt[b,y,x] = value[b,x,y]*mask ----------
__global__ void k_vtrans(const float* __restrict__ val, float* __restrict__ vt,
                         const int* __restrict__ srcL, const int* __restrict__ melL) {
    __shared__ float s[32][33];
    int b = blockIdx.z;
    int x0 = blockIdx.x * 32, y0 = blockIdx.y * 32;
    int sl = srcL[b], ml = melL[b];
    const float* vp = val + (size_t)b * 512 * 1024;
    float* op = vt + (size_t)b * 1024 * 512;
    for (int i = threadIdx.y; i < 32; i += 8) {
        int x = x0 + i, y = y0 + threadIdx.x;
        float v = vp[(size_t)x * 1024 + y];
        s[i][threadIdx.x] = (x < sl && y < ml) ? v : 0.f;
    }
    __syncthreads();
    for (int j = threadIdx.y; j < 32; j += 8)
        op[(size_t)(y0 + j) * 512 + x0 + threadIdx.x] = s[threadIdx.x][j];
}

// ---------- MAS forward DP (one block per batch, bit-exact replay) ----------
__global__ void k_masdp(const float* __restrict__ vt, const int* __restrict__ srcL,
                        const int* __restrict__ melL, unsigned* __restrict__ dir) {
    __shared__ float sv[512];
    int b = blockIdx.x, x = threadIdx.x;
    int sl = srcL[b], ml = melL[b];
    int lane = x & 31, wid = x >> 5;
    float v = 0.f;
    for (int j = 0; j < 1024; ++j) {
        sv[x] = v;
        __syncthreads();
        float v0 = x ? sv[x - 1] : NEGF;
        float val = vt[((size_t)b * 1024 + j) * 512 + x];
        bool d = (v >= v0);
        float vmax = d ? v : v0;
        float vnew = (x <= j) ? (vmax + val) : NEGF;
        bool dm = (x < sl && j < ml) ? d : true;
        unsigned bal = __ballot_sync(0xffffffffu, dm);
        if (lane == 0) dir[((size_t)b * 1024 + j) * 16 + wid] = bal;
        v = vnew;
        __syncthreads();
    }
}

// ---------- MAS backtrack (serial per batch) ----------
__global__ void k_masbt(const unsigned* __restrict__ dir, const int* __restrict__ srcL,
                        int* __restrict__ idxout) {
    int b = threadIdx.x;
    if (b >= 32) return;
    int idx = srcL[b] - 1;
    for (int y = 1023; y >= 0; --y) {
        idxout[b * 1024 + y] = idx;
        unsigned w = dir[((size_t)b * 1024 + y) * 16 + (idx >> 5)];
        idx += (int)((w >> (idx & 31)) & 1u) - 1;
    }
}

// ---------- expand: out[b,y,:] = x[b, idx(b,y), :] within mel mask ----------
__global__ void k_expand(const float* __restrict__ X, const int* __restrict__ idx,
                         const int* __restrict__ srcL, const int* __restrict__ melL,
                         float* __restrict__ out) {
    int row = blockIdx.x;  // b*1024 + y
    int b = row >> 10, y = row & 1023;
    int d = threadIdx.x;
    float o = 0.f;
    if (y < melL[b]) {
        int ix = idx[row];
        if (ix >= 0 && ix < srcL[b])
            o = X[((size_t)(b << 9) + ix) * 256 + d];
    }
    out[(size_t)row * 256 + d] = o;
}

extern "C" void kernel_launch(void* const* d_in, const int* in_sizes, int n_in,
                              void* d_out, int out_size) {
    const int* tokens = (const int*)d_in[0];
    const int* srcL   = (const int*)d_in[1];
    const int* melL   = (const int*)d_in[2];
    const float* value = (const float*)d_in[3];
    const float* embed = (const float*)d_in[4];
    const float* pos   = (const float*)d_in[5];
    const float* wq = (const float*)d_in[6];  const float* bq = (const float*)d_in[7];
    const float* wk = (const float*)d_in[8];  const float* bk = (const float*)d_in[9];
    const float* wv = (const float*)d_in[10]; const float* bv = (const float*)d_in[11];
    const float* wo = (const float*)d_in[12]; const float* bo = (const float*)d_in[13];
    const float* ln1g = (const float*)d_in[14]; const float* ln1b = (const float*)d_in[15];
    const float* c1w = (const float*)d_in[16]; const float* c1b = (const float*)d_in[17];
    const float* c2w = (const float*)d_in[18]; const float* c2b = (const float*)d_in[19];
    const float* ln2g = (const float*)d_in[20]; const float* ln2b = (const float*)d_in[21];
    float* out = (float*)d_out;

    float *px, *pq, *pk, *pv, *po, *pt, *ps, *ph, *pvt, *pw1, *pw2;
    unsigned* pdir; int* pidx;
    cudaGetSymbolAddress((void**)&px, g_x);
    cudaGetSymbolAddress((void**)&pq, g_q);
    cudaGetSymbolAddress((void**)&pk, g_k);
    cudaGetSymbolAddress((void**)&pv, g_v);
    cudaGetSymbolAddress((void**)&po, g_o);
    cudaGetSymbolAddress((void**)&pt, g_t);
    cudaGetSymbolAddress((void**)&ps, g_s);
    cudaGetSymbolAddress((void**)&ph, g_h);
    cudaGetSymbolAddress((void**)&pvt, g_vt);
    cudaGetSymbolAddress((void**)&pw1, g_w1t);
    cudaGetSymbolAddress((void**)&pw2, g_w2t);
    cudaGetSymbolAddress((void**)&pdir, g_dir);
    cudaGetSymbolAddress((void**)&pidx, g_idx);

    dim3 blk256(256);
    // weight transposes: c1_w [L,1024,256,9] -> [L,9,256,1024]; c2_w [L,256,1024,9] -> [L,9,1024,256]
    k_wtrans<<<dim3(72, 32, 4), dim3(32, 8)>>>(c1w, pw1, 1024, 256);
    k_wtrans<<<dim3(288, 8, 4), dim3(32, 8)>>>(c2w, pw2, 256, 1024);
    // value transpose + mask
    k_vtrans<<<dim3(16, 32, 32), dim3(32, 8)>>>(value, pvt, srcL, melL);
    // embedding
    k_embed<<<16384, blk256>>>(tokens, embed, pos, px);

    for (int l = 0; l < 4; ++l) {
        const float* wq_l = wq + (size_t)l * 65536; const float* bq_l = bq + l * 256;
        const float* wk_l = wk + (size_t)l * 65536; const float* bk_l = bk + l * 256;
        const float* wv_l = wv + (size_t)l * 65536; const float* bv_l = bv + l * 256;
        const float* wo_l = wo + (size_t)l * 65536; const float* bo_l = bo + l * 256;

        k_gemm_bias<<<dim3(4, 256), blk256>>>(px, wq_l, bq_l, pq);
        k_gemm_bias<<<dim3(4, 256), blk256>>>(px, wk_l, bk_l, pk);
        k_gemm_bias<<<dim3(4, 256), blk256>>>(px, wv_l, bv_l, pv);
        k_scores<<<dim3(8, 8, 64), blk256>>>(pq, pk, ps, srcL);
        k_softmax<<<32768, 128>>>(ps);
        k_attnout<<<dim3(2, 8, 64), blk256>>>(ps, pv, po);
        k_gemm_bias<<<dim3(4, 256), blk256>>>(po, wo_l, bo_l, pt);
        k_lnres<<<16384, blk256>>>(pt, px, ln1g + l * 256, ln1b + l * 256, srcL, px);

        k_conv1<<<dim3(16, 256), blk256>>>(px, pw1 + (size_t)l * 2359296, c1b + l * 1024, ph);
        k_conv2<<<dim3(4, 256), blk256>>>(ph, pw2 + (size_t)l * 2359296, c2b + l * 256, pt);
        k_lnres<<<16384, blk256>>>(pt, px, ln2g + l * 256, ln2b + l * 256, srcL, px);
    }

    k_masdp<<<32, 512>>>(pvt, srcL, melL, pdir);
    k_masbt<<<1, 32>>>(pdir, srcL, pidx);
    k_expand<<<32768, blk256>>>(px, pidx, srcL, melL, out);
}

// round 7
// speedup vs baseline: 1.3464x; 1.3464x over previous
#include <cuda_runtime.h>
#include <math.h>

#define NEGF (-1e9f)

// ---------- scratch (device globals; allocation is forbidden) ----------
__device__ float    g_x [4194304];   // [B*TX, 256]
__device__ float    g_q [4194304];
__device__ float    g_k [4194304];
__device__ float    g_v [4194304];
__device__ float    g_o [4194304];
__device__ float    g_t [4194304];
__device__ float    g_s [16777216];  // [B*H*TX, TX]
__device__ float    g_h [16777216];  // [B*TX, 1024]
__device__ float    g_vt[16777216];  // [B, TY, TX]
__device__ float    g_w1t[9437184];  // [L,9,256,1024]
__device__ float    g_w2t[9437184];  // [L,9,1024,256]
__device__ unsigned g_dir[524288];   // [B,TY,16]
__device__ int      g_idx[32768];    // [B,TY]

// ================= tf32 split-precision MMA machinery =================
// Block tile 128x128, BK=16. 8 warps: wm = w&3 (4 x 32 rows), wn = w>>2 (2 x 64 cols).
// Warp tile 32x64 = 2 m16 x 8 n8 mma tiles. Split: v = hi + lo (both tf32).

__device__ __forceinline__ void cvt2(float v, unsigned& h, unsigned& l) {
    unsigned hh;
    asm("cvt.rna.tf32.f32 %0, %1;" : "=r"(hh) : "f"(v));
    float r = v - __uint_as_float(hh);
    unsigned ll;
    asm("cvt.rna.tf32.f32 %0, %1;" : "=r"(ll) : "f"(r));
    h = hh; l = ll;
}

__device__ __forceinline__ void mma8(float c[4], const unsigned a[4], const unsigned b[2]) {
    asm volatile(
        "mma.sync.aligned.m16n8k8.row.col.f32.tf32.tf32.f32 "
        "{%0,%1,%2,%3},{%4,%5,%6,%7},{%8,%9},{%0,%1,%2,%3};\n"
        : "+f"(c[0]), "+f"(c[1]), "+f"(c[2]), "+f"(c[3])
        : "r"(a[0]), "r"(a[1]), "r"(a[2]), "r"(a[3]), "r"(b[0]), "r"(b[1]));
}

// As: [128][20] m-major (cols 0..15 used). Bs: [16][136] k-major (cols 0..127).
#define ASTR 20
#define BSTR 136

__device__ __forceinline__ void mma_tile(const unsigned* __restrict__ AsH,
                                         const unsigned* __restrict__ AsL,
                                         const unsigned* __restrict__ BsH,
                                         const unsigned* __restrict__ BsL,
                                         int wm, int wn, int g, int tig,
                                         float (*acc)[4]) {
#pragma unroll
    for (int ks = 0; ks < 16; ks += 8) {
        unsigned aH[2][4], aL[2][4];
#pragma unroll
        for (int i = 0; i < 2; ++i) {
            int base = (wm * 32 + i * 16 + g) * ASTR + ks + tig;
            aH[i][0] = AsH[base];           aH[i][1] = AsH[base + 8 * ASTR];
            aH[i][2] = AsH[base + 4];       aH[i][3] = AsH[base + 8 * ASTR + 4];
            aL[i][0] = AsL[base];           aL[i][1] = AsL[base + 8 * ASTR];
            aL[i][2] = AsL[base + 4];       aL[i][3] = AsL[base + 8 * ASTR + 4];
        }
#pragma unroll
        for (int jh = 0; jh < 8; jh += 4) {
            unsigned bH[4][2], bL[4][2];
#pragma unroll
            for (int j = 0; j < 4; ++j) {
                int base = (ks + tig) * BSTR + wn * 64 + (jh + j) * 8 + g;
                bH[j][0] = BsH[base]; bH[j][1] = BsH[base + 4 * BSTR];
                bL[j][0] = BsL[base]; bL[j][1] = BsL[base + 4 * BSTR];
            }
#pragma unroll
            for (int i = 0; i < 2; ++i)
#pragma unroll
                for (int j = 0; j < 4; ++j) {
                    float* c = acc[i * 8 + jh + j];
                    mma8(c, aH[i], bH[j]);
                    mma8(c, aL[i], bH[j]);
                    mma8(c, aH[i], bL[j]);
                }
        }
    }
}

// load 128x16 A tile (row-major src, leading dim ld) into split smem
__device__ __forceinline__ void loadA(unsigned* AsH, unsigned* AsL,
                                      const float* __restrict__ src, int ld, int tid) {
    int row = tid >> 1, c = (tid & 1) * 8;
    const float* p = src + (size_t)row * ld + c;
#pragma unroll
    for (int q = 0; q < 2; ++q) {
        float4 v = *(const float4*)(p + q * 4);
        unsigned h0, l0, h1, l1, h2, l2, h3, l3;
        cvt2(v.x, h0, l0); cvt2(v.y, h1, l1); cvt2(v.z, h2, l2); cvt2(v.w, h3, l3);
        int o = row * ASTR + c + q * 4;
        *(uint4*)&AsH[o] = make_uint4(h0, h1, h2, h3);
        *(uint4*)&AsL[o] = make_uint4(l0, l1, l2, l3);
    }
}

// guarded A tile load (conv halo): p points at this thread's row start; ok=row valid
__device__ __forceinline__ void loadA_g(unsigned* AsH, unsigned* AsL,
                                        const float* __restrict__ p, int row, int c, bool ok) {
#pragma unroll
    for (int q = 0; q < 2; ++q) {
        float4 v = ok ? *(const float4*)(p + q * 4) : make_float4(0.f, 0.f, 0.f, 0.f);
        unsigned h0, l0, h1, l1, h2, l2, h3, l3;
        cvt2(v.x, h0, l0); cvt2(v.y, h1, l1); cvt2(v.z, h2, l2); cvt2(v.w, h3, l3);
        int o = row * ASTR + c + q * 4;
        *(uint4*)&AsH[o] = make_uint4(h0, h1, h2, h3);
        *(uint4*)&AsL[o] = make_uint4(l0, l1, l2, l3);
    }
}

// load 16x128 B tile, src k-major rows (leading dim ld)
__device__ __forceinline__ void loadB(unsigned* BsH, unsigned* BsL,
                                      const float* __restrict__ src, int ld, int tid) {
#pragma unroll
    for (int i = 0; i < 2; ++i) {
        int idx = tid + i * 256;
        int kr = idx >> 5, c = (idx & 31) * 4;
        float4 v = *(const float4*)&src[(size_t)kr * ld + c];
        unsigned h0, l0, h1, l1, h2, l2, h3, l3;
        cvt2(v.x, h0, l0); cvt2(v.y, h1, l1); cvt2(v.z, h2, l2); cvt2(v.w, h3, l3);
        int o = kr * BSTR + c;
        *(uint4*)&BsH[o] = make_uint4(h0, h1, h2, h3);
        *(uint4*)&BsL[o] = make_uint4(l0, l1, l2, l3);
    }
}

// load 128x16 B tile transposed (src n-major rows of k values), into Bs[k][n]
__device__ __forceinline__ void loadBT(unsigned* BsH, unsigned* BsL,
                                       const float* __restrict__ src, int ld, int tid) {
#pragma unroll
    for (int i = 0; i < 2; ++i) {
        int idx = tid + i * 256;
        int n = idx & 127, kq = (idx >> 7) * 4;
        float4 v = *(const float4*)&src[(size_t)n * ld + kq];
        unsigned h, l;
        cvt2(v.x, h, l); BsH[(kq + 0) * BSTR + n] = h; BsL[(kq + 0) * BSTR + n] = l;
        cvt2(v.y, h, l); BsH[(kq + 1) * BSTR + n] = h; BsL[(kq + 1) * BSTR + n] = l;
        cvt2(v.z, h, l); BsH[(kq + 2) * BSTR + n] = h; BsL[(kq + 2) * BSTR + n] = l;
        cvt2(v.w, h, l); BsH[(kq + 3) * BSTR + n] = h; BsL[(kq + 3) * BSTR + n] = l;
    }
}

// ================= GEMM-like kernels =================

// C[16384,256] = A[16384,256] @ W[256,256] + bias
__global__ void __launch_bounds__(256, 2)
k_gemm_bias(const float* __restrict__ A, const float* __restrict__ W,
            const float* __restrict__ bias, float* __restrict__ C) {
    __shared__ unsigned AsH[128 * ASTR], AsL[128 * ASTR], BsH[16 * BSTR], BsL[16 * BSTR];
    int tid = threadIdx.x, w = tid >> 5, lane = tid & 31;
    int wm = w & 3, wn = w >> 2, g = lane >> 2, tig = lane & 3;
    int n0 = blockIdx.x * 128, m0 = blockIdx.y * 128;
    float acc[16][4] = {};
    for (int k0 = 0; k0 < 256; k0 += 16) {
        loadA(AsH, AsL, A + (size_t)m0 * 256 + k0, 256, tid);
        loadB(BsH, BsL, W + (size_t)k0 * 256 + n0, 256, tid);
        __syncthreads();
        mma_tile(AsH, AsL, BsH, BsL, wm, wn, g, tig, acc);
        __syncthreads();
    }
#pragma unroll
    for (int i = 0; i < 2; ++i)
#pragma unroll
        for (int j = 0; j < 8; ++j) {
            int m = m0 + wm * 32 + i * 16 + g;
            int n = n0 + wn * 64 + j * 8 + 2 * tig;
            float b0 = bias[n], b1 = bias[n + 1];
            float2 r0 = {acc[i * 8 + j][0] + b0, acc[i * 8 + j][1] + b1};
            float2 r1 = {acc[i * 8 + j][2] + b0, acc[i * 8 + j][3] + b1};
            *(float2*)&C[(size_t)m * 256 + n] = r0;
            *(float2*)&C[(size_t)(m + 8) * 256 + n] = r1;
        }
}

// scores S[bh,q,k] = scale*Q.K^T, key-pad mask
__global__ void __launch_bounds__(256, 2)
k_scores(const float* __restrict__ Q, const float* __restrict__ K,
         float* __restrict__ S, const int* __restrict__ srcL) {
    __shared__ unsigned AsH[128 * ASTR], AsL[128 * ASTR], BsH[16 * BSTR], BsL[16 * BSTR];
    int tid = threadIdx.x, w = tid >> 5, lane = tid & 31;
    int wm = w & 3, wn = w >> 2, g = lane >> 2, tig = lane & 3;
    int n0 = blockIdx.x * 128, m0 = blockIdx.y * 128, bh = blockIdx.z;
    int b = bh >> 1, h = bh & 1;
    const float* qb = Q + (size_t)b * 512 * 256 + h * 128;
    const float* kb = K + (size_t)b * 512 * 256 + h * 128;
    float acc[16][4] = {};
    for (int k0 = 0; k0 < 128; k0 += 16) {
        loadA(AsH, AsL, qb + (size_t)m0 * 256 + k0, 256, tid);
        loadBT(BsH, BsL, kb + (size_t)n0 * 256 + k0, 256, tid);
        __syncthreads();
        mma_tile(AsH, AsL, BsH, BsL, wm, wn, g, tig, acc);
        __syncthreads();
    }
    int sl = srcL[b];
    const float scale = 0.08838834764831845f;  // 1/sqrt(128)
#pragma unroll
    for (int i = 0; i < 2; ++i)
#pragma unroll
        for (int j = 0; j < 8; ++j) {
            int m = m0 + wm * 32 + i * 16 + g;
            int n = n0 + wn * 64 + j * 8 + 2 * tig;
            bool p0 = (n >= sl), p1 = (n + 1 >= sl);
            float2 r0 = {p0 ? NEGF : acc[i * 8 + j][0] * scale,
                         p1 ? NEGF : acc[i * 8 + j][1] * scale};
            float2 r1 = {p0 ? NEGF : acc[i * 8 + j][2] * scale,
                         p1 ? NEGF : acc[i * 8 + j][3] * scale};
            *(float2*)&S[((size_t)bh * 512 + m) * 512 + n] = r0;
            *(float2*)&S[((size_t)bh * 512 + m + 8) * 512 + n] = r1;
        }
}

// attn out: O[b,q,h*128+d] = sum_k S[bh,q,k] V[b,k,h*128+d]
__global__ void __launch_bounds__(256, 2)
k_attnout(const float* __restrict__ S, const float* __restrict__ V, float* __restrict__ O) {
    __shared__ unsigned AsH[128 * ASTR], AsL[128 * ASTR], BsH[16 * BSTR], BsL[16 * BSTR];
    int tid = threadIdx.x, w = tid >> 5, lane = tid & 31;
    int wm = w & 3, wn = w >> 2, g = lane >> 2, tig = lane & 3;
    int m0 = blockIdx.y * 128, bh = blockIdx.z;
    int b = bh >> 1, h = bh & 1;
    const float* sb = S + (size_t)bh * 512 * 512;
    const float* vb = V + (size_t)b * 512 * 256 + h * 128;
    float acc[16][4] = {};
    for (int k0 = 0; k0 < 512; k0 += 16) {
        loadA(AsH, AsL, sb + (size_t)m0 * 512 + k0, 512, tid);
        loadB(BsH, BsL, vb + (size_t)k0 * 256, 256, tid);
        __syncthreads();
        mma_tile(AsH, AsL, BsH, BsL, wm, wn, g, tig, acc);
        __syncthreads();
    }
#pragma unroll
    for (int i = 0; i < 2; ++i)
#pragma unroll
        for (int j = 0; j < 8; ++j) {
            int m = m0 + wm * 32 + i * 16 + g;
            int n = wn * 64 + j * 8 + 2 * tig;
            float2 r0 = {acc[i * 8 + j][0], acc[i * 8 + j][1]};
            float2 r1 = {acc[i * 8 + j][2], acc[i * 8 + j][3]};
            *(float2*)&O[((size_t)b * 512 + m) * 256 + h * 128 + n] = r0;
            *(float2*)&O[((size_t)b * 512 + m + 8) * 256 + h * 128 + n] = r1;
        }
}

// conv1: H = relu(im2col(X) @ W1t + b1), X[16384,256] -> H[16384,1024]
__global__ void __launch_bounds__(256, 2)
k_conv1(const float* __restrict__ X, const float* __restrict__ Wt,
        const float* __restrict__ bias, float* __restrict__ H) {
    __shared__ unsigned AsH[128 * ASTR], AsL[128 * ASTR], BsH[16 * BSTR], BsL[16 * BSTR];
    int tid = threadIdx.x, w = tid >> 5, lane = tid & 31;
    int wm = w & 3, wn = w >> 2, g = lane >> 2, tig = lane & 3;
    int n0 = blockIdx.x * 128, m0 = blockIdx.y * 128;
    int bbase = (m0 >> 9) << 9, tbase = m0 & 511;
    int arow = tid >> 1, ac = (tid & 1) * 8;
    float acc[16][4] = {};
    for (int dk = 0; dk < 9; ++dk) {
        int t = tbase + arow + dk - 4;
        bool ok = ((unsigned)t < 512u);
        const float* ap = X + ((size_t)bbase + t) * 256 + ac;
        const float* wdk = Wt + (size_t)dk * 262144;
        for (int k0 = 0; k0 < 256; k0 += 16) {
            loadA_g(AsH, AsL, ap + k0, arow, ac, ok);
            loadB(BsH, BsL, wdk + (size_t)k0 * 1024 + n0, 1024, tid);
            __syncthreads();
            mma_tile(AsH, AsL, BsH, BsL, wm, wn, g, tig, acc);
            __syncthreads();
        }
    }
#pragma unroll
    for (int i = 0; i < 2; ++i)
#pragma unroll
        for (int j = 0; j < 8; ++j) {
            int m = m0 + wm * 32 + i * 16 + g;
            int n = n0 + wn * 64 + j * 8 + 2 * tig;
            float b0 = bias[n], b1 = bias[n + 1];
            float2 r0 = {fmaxf(acc[i * 8 + j][0] + b0, 0.f), fmaxf(acc[i * 8 + j][1] + b1, 0.f)};
            float2 r1 = {fmaxf(acc[i * 8 + j][2] + b0, 0.f), fmaxf(acc[i * 8 + j][3] + b1, 0.f)};
            *(float2*)&H[(size_t)m * 1024 + n] = r0;
            *(float2*)&H[(size_t)(m + 8) * 1024 + n] = r1;
        }
}

// conv2: T = im2col(H) @ W2t + b2, H[16384,1024] -> T[16384,256]
__global__ void __launch_bounds__(256, 2)
k_conv2(const float* __restrict__ Hi, const float* __restrict__ Wt,
        const float* __restrict__ bias, float* __restrict__ T) {
    __shared__ unsigned AsH[128 * ASTR], AsL[128 * ASTR], BsH[16 * BSTR], BsL[16 * BSTR];
    int tid = threadIdx.x, w = tid >> 5, lane = tid & 31;
    int wm = w & 3, wn = w >> 2, g = lane >> 2, tig = lane & 3;
    int n0 = blockIdx.x * 128, m0 = blockIdx.y * 128;
    int bbase = (m0 >> 9) << 9, tbase = m0 & 511;
    int arow = tid >> 1, ac = (tid & 1) * 8;
    float acc[16][4] = {};
    for (int dk = 0; dk < 9; ++dk) {
        int t = tbase + arow + dk - 4;
        bool ok = ((unsigned)t < 512u);
        const float* ap = Hi + ((size_t)bbase + t) * 1024 + ac;
        const float* wdk = Wt + (size_t)dk * 262144;
        for (int k0 = 0; k0 < 1024; k0 += 16) {
            loadA_g(AsH, AsL, ap + k0, arow, ac, ok);
            loadB(BsH, BsL, wdk + (size_t)k0 * 256 + n0, 256, tid);
            __syncthreads();
            mma_tile(AsH, AsL, BsH, BsL, wm, wn, g, tig, acc);
            __syncthreads();
        }
    }
#pragma unroll
    for (int i = 0; i < 2; ++i)
#pragma unroll
        for (int j = 0; j < 8; ++j) {
            int m = m0 + wm * 32 + i * 16 + g;
            int n = n0 + wn * 64 + j * 8 + 2 * tig;
            float b0 = bias[n], b1 = bias[n + 1];
            float2 r0 = {acc[i * 8 + j][0] + b0, acc[i * 8 + j][1] + b1};
            float2 r1 = {acc[i * 8 + j][2] + b0, acc[i * 8 + j][3] + b1};
            *(float2*)&T[(size_t)m * 256 + n] = r0;
            *(float2*)&T[(size_t)(m + 8) * 256 + n] = r1;
        }
}

// ================= elementwise / DP kernels (unchanged from passing round) =================

__global__ void k_embed(const int* __restrict__ tok, const float* __restrict__ emb,
                        const float* __restrict__ pos, float* __restrict__ x) {
    int row = blockIdx.x;
    int d = threadIdx.x;
    int t = row & 511;
    int id = tok[row];
    x[(size_t)row * 256 + d] = emb[(size_t)id * 256 + d] + pos[(size_t)t * 256 + d];
}

__global__ void k_softmax(float* __restrict__ S) {
    __shared__ float red[4];
    size_t row = blockIdx.x;
    float4 v = ((float4*)(S + row * 512))[threadIdx.x];
    int lane = threadIdx.x & 31, wid = threadIdx.x >> 5;
    float m = fmaxf(fmaxf(v.x, v.y), fmaxf(v.z, v.w));
#pragma unroll
    for (int o = 16; o > 0; o >>= 1) m = fmaxf(m, __shfl_xor_sync(~0u, m, o));
    if (lane == 0) red[wid] = m;
    __syncthreads();
    m = fmaxf(fmaxf(red[0], red[1]), fmaxf(red[2], red[3]));
    __syncthreads();
    v.x = expf(v.x - m); v.y = expf(v.y - m); v.z = expf(v.z - m); v.w = expf(v.w - m);
    float s = v.x + v.y + v.z + v.w;
#pragma unroll
    for (int o = 16; o > 0; o >>= 1) s += __shfl_xor_sync(~0u, s, o);
    if (lane == 0) red[wid] = s;
    __syncthreads();
    s = red[0] + red[1] + red[2] + red[3];
    float inv = 1.0f / s;
    v.x *= inv; v.y *= inv; v.z *= inv; v.w *= inv;
    ((float4*)(S + row * 512))[threadIdx.x] = v;
}

__global__ void k_lnres(const float* __restrict__ t, const float* __restrict__ res,
                        const float* __restrict__ gam, const float* __restrict__ bet,
                        const int* __restrict__ srcL, float* __restrict__ out) {
    __shared__ float red[8];
    int row = blockIdx.x, d = threadIdx.x;
    size_t off = (size_t)row * 256 + d;
    float val = t[off] + res[off];
    float s = val;
#pragma unroll
    for (int o = 16; o > 0; o >>= 1) s += __shfl_xor_sync(~0u, s, o);
    if ((d & 31) == 0) red[d >> 5] = s;
    __syncthreads();
    float tot = 0.f;
#pragma unroll
    for (int i = 0; i < 8; ++i) tot += red[i];
    float mean = tot * (1.0f / 256.0f);
    float dv = val - mean;
    __syncthreads();
    float s2 = dv * dv;
#pragma unroll
    for (int o = 16; o > 0; o >>= 1) s2 += __shfl_xor_sync(~0u, s2, o);
    if ((d & 31) == 0) red[d >> 5] = s2;
    __syncthreads();
    float tot2 = 0.f;
#pragma unroll
    for (int i = 0; i < 8; ++i) tot2 += red[i];
    float o = dv * rsqrtf(tot2 * (1.0f / 256.0f) + 1e-5f) * gam[d] + bet[d];
    if ((row & 511) >= srcL[row >> 9]) o = 0.f;
    out[off] = o;
}

__global__ void k_wtrans(const float* __restrict__ src, float* __restrict__ dst, int R, int C) {
    __shared__ float s[32][33];
    int l = blockIdx.z;
    int CD = C * 9;
    int cd0 = blockIdx.x * 32, r0 = blockIdx.y * 32;
    const float* sp = src + (size_t)l * R * CD;
    float* dp = dst + (size_t)l * 9 * C * R;
    for (int i = threadIdx.y; i < 32; i += 8)
        s[i][threadIdx.x] = sp[(size_t)(r0 + i) * CD + cd0 + threadIdx.x];
    __syncthreads();
    for (int j = threadIdx.y; j < 32; j += 8) {
        int cd = cd0 + j;
        int c = cd / 9, dk = cd % 9;
        dp[((size_t)dk * C + c) * R + r0 + threadIdx.x] = s[threadIdx.x][j];
    }
}

__global__ void k_vtrans(const float* __restrict__ val, float* __restrict__ vt,
                         const int* __restrict__ srcL, const int* __restrict__ melL) {
    __shared__ float s[32][33];
    int b = blockIdx.z;
    int x0 = blockIdx.x * 32, y0 = blockIdx.y * 32;
    int sl = srcL[b], ml = melL[b];
    const float* vp = val + (size_t)b * 512 * 1024;
    float* op = vt + (size_t)b * 1024 * 512;
    for (int i = threadIdx.y; i < 32; i += 8) {
        int x = x0 + i, y = y0 + threadIdx.x;
        float v = vp[(size_t)x * 1024 + y];
        s[i][threadIdx.x] = (x < sl && y < ml) ? v : 0.f;
    }
    __syncthreads();
    for (int j = threadIdx.y; j < 32; j += 8)
        op[(size_t)(y0 + j) * 512 + x0 + threadIdx.x] = s[threadIdx.x][j];
}

__global__ void k_masdp(const float* __restrict__ vt, const int* __restrict__ srcL,
                        const int* __restrict__ melL, unsigned* __restrict__ dir) {
    __shared__ float sv[512];
    int b = blockIdx.x, x = threadIdx.x;
    int sl = srcL[b], ml = melL[b];
    int lane = x & 31, wid = x >> 5;
    float v = 0.f;
    for (int j = 0; j < 1024; ++j) {
        sv[x] = v;
        __syncthreads();
        float v0 = x ? sv[x - 1] : NEGF;
        float val = vt[((size_t)b * 1024 + j) * 512 + x];
        bool d = (v >= v0);
        float vmax = d ? v : v0;
        float vnew = (x <= j) ? (vmax + val) : NEGF;
        bool dm = (x < sl && j < ml) ? d : true;
        unsigned bal = __ballot_sync(0xffffffffu, dm);
        if (lane == 0) dir[((size_t)b * 1024 + j) * 16 + wid] = bal;
        v = vnew;
        __syncthreads();
    }
}

__global__ void k_masbt(const unsigned* __restrict__ dir, const int* __restrict__ srcL,
                        int* __restrict__ idxout) {
    int b = threadIdx.x;
    if (b >= 32) return;
    int idx = srcL[b] - 1;
    for (int y = 1023; y >= 0; --y) {
        idxout[b * 1024 + y] = idx;
        unsigned w = dir[((size_t)b * 1024 + y) * 16 + (idx >> 5)];
        idx += (int)((w >> (idx & 31)) & 1u) - 1;
    }
}

__global__ void k_expand(const float* __restrict__ X, const int* __restrict__ idx,
                         const int* __restrict__ srcL, const int* __restrict__ melL,
                         float* __restrict__ out) {
    int row = blockIdx.x;
    int b = row >> 10, y = row & 1023;
    int d = threadIdx.x;
    float o = 0.f;
    if (y < melL[b]) {
        int ix = idx[row];
        if (ix >= 0 && ix < srcL[b])
            o = X[((size_t)(b << 9) + ix) * 256 + d];
    }
    out[(size_t)row * 256 + d] = o;
}

extern "C" void kernel_launch(void* const* d_in, const int* in_sizes, int n_in,
                              void* d_out, int out_size) {
    const int* tokens = (const int*)d_in[0];
    const int* srcL   = (const int*)d_in[1];
    const int* melL   = (const int*)d_in[2];
    const float* value = (const float*)d_in[3];
    const float* embed = (const float*)d_in[4];
    const float* pos   = (const float*)d_in[5];
    const float* wq = (const float*)d_in[6];  const float* bq = (const float*)d_in[7];
    const float* wk = (const float*)d_in[8];  const float* bk = (const float*)d_in[9];
    const float* wv = (const float*)d_in[10]; const float* bv = (const float*)d_in[11];
    const float* wo = (const float*)d_in[12]; const float* bo = (const float*)d_in[13];
    const float* ln1g = (const float*)d_in[14]; const float* ln1b = (const float*)d_in[15];
    const float* c1w = (const float*)d_in[16]; const float* c1b = (const float*)d_in[17];
    const float* c2w = (const float*)d_in[18]; const float* c2b = (const float*)d_in[19];
    const float* ln2g = (const float*)d_in[20]; const float* ln2b = (const float*)d_in[21];
    float* out = (float*)d_out;

    float *px, *pq, *pk, *pv, *po, *pt, *ps, *ph, *pvt, *pw1, *pw2;
    unsigned* pdir; int* pidx;
    cudaGetSymbolAddress((void**)&px, g_x);
    cudaGetSymbolAddress((void**)&pq, g_q);
    cudaGetSymbolAddress((void**)&pk, g_k);
    cudaGetSymbolAddress((void**)&pv, g_v);
    cudaGetSymbolAddress((void**)&po, g_o);
    cudaGetSymbolAddress((void**)&pt, g_t);
    cudaGetSymbolAddress((void**)&ps, g_s);
    cudaGetSymbolAddress((void**)&ph, g_h);
    cudaGetSymbolAddress((void**)&pvt, g_vt);
    cudaGetSymbolAddress((void**)&pw1, g_w1t);
    cudaGetSymbolAddress((void**)&pw2, g_w2t);
    cudaGetSymbolAddress((void**)&pdir, g_dir);
    cudaGetSymbolAddress((void**)&pidx, g_idx);

    dim3 blk256(256);
    k_wtrans<<<dim3(72, 32, 4), dim3(32, 8)>>>(c1w, pw1, 1024, 256);
    k_wtrans<<<dim3(288, 8, 4), dim3(32, 8)>>>(c2w, pw2, 256, 1024);
    k_vtrans<<<dim3(16, 32, 32), dim3(32, 8)>>>(value, pvt, srcL, melL);
    k_embed<<<16384, blk256>>>(tokens, embed, pos, px);

    for (int l = 0; l < 4; ++l) {
        const float* wq_l = wq + (size_t)l * 65536; const float* bq_l = bq + l * 256;
        const float* wk_l = wk + (size_t)l * 65536; const float* bk_l = bk + l * 256;
        const float* wv_l = wv + (size_t)l * 65536; const float* bv_l = bv + l * 256;
        const float* wo_l = wo + (size_t)l * 65536; const float* bo_l = bo + l * 256;

        k_gemm_bias<<<dim3(2, 128), blk256>>>(px, wq_l, bq_l, pq);
        k_gemm_bias<<<dim3(2, 128), blk256>>>(px, wk_l, bk_l, pk);
        k_gemm_bias<<<dim3(2, 128), blk256>>>(px, wv_l, bv_l, pv);
        k_scores<<<dim3(4, 4, 64), blk256>>>(pq, pk, ps, srcL);
        k_softmax<<<32768, 128>>>(ps);
        k_attnout<<<dim3(1, 4, 64), blk256>>>(ps, pv, po);
        k_gemm_bias<<<dim3(2, 128), blk256>>>(po, wo_l, bo_l, pt);
        k_lnres<<<16384, blk256>>>(pt, px, ln1g + l * 256, ln1b + l * 256, srcL, px);

        k_conv1<<<dim3(8, 128), blk256>>>(px, pw1 + (size_t)l * 2359296, c1b + l * 1024, ph);
        k_conv2<<<dim3(2, 128), blk256>>>(ph, pw2 + (size_t)l * 2359296, c2b + l * 256, pt);
        k_lnres<<<16384, blk256>>>(pt, px, ln2g + l * 256, ln2b + l * 256, srcL, px);
    }

    k_masdp<<<32, 512>>>(pvt, srcL, melL, pdir);
    k_masbt<<<1, 32>>>(pdir, srcL, pidx);
    k_expand<<<32768, blk256>>>(px, pidx, srcL, melL, out);
}

// round 8
// speedup vs baseline: 2.1694x; 1.6113x over previous
#include <cuda_runtime.h>
#include <cuda_fp16.h>
#include <math.h>

#define NEGF (-1e9f)

typedef unsigned short ushort_t;

// ---------- scratch (device globals; allocation is forbidden) ----------
__device__ float    g_x [4194304];    // [B*TX, 256] fp32 (residual / expand)
__device__ float    g_t [4194304];    // fp32 temp
__device__ float    g_s [16777216];   // attn scores fp32
__device__ float    g_vt[16777216];   // [B, TY, TX]
__device__ float    g_w1t[9437184];   // [L,9,256,1024] fp32 transposed
__device__ float    g_w2t[9437184];   // [L,9,1024,256]
__device__ ushort_t g_xh[4194304],  g_xl[4194304];
__device__ ushort_t g_qh[4194304],  g_ql[4194304];
__device__ ushort_t g_kh[4194304],  g_kl[4194304];
__device__ ushort_t g_vh[4194304],  g_vl[4194304];
__device__ ushort_t g_oh[4194304],  g_ol[4194304];
__device__ ushort_t g_sh[16777216], g_sl[16777216];
__device__ ushort_t g_hh[16777216], g_hl[16777216];
__device__ unsigned g_w1h[4718592], g_w1l[4718592];   // pair-packed [kp][1024]
__device__ unsigned g_w2h[4718592], g_w2l[4718592];   // pair-packed [kp][256]
__device__ unsigned g_wqh[131072], g_wql[131072], g_wkh[131072], g_wkl[131072];
__device__ unsigned g_wvh[131072], g_wvl[131072], g_woh[131072], g_wol[131072];
__device__ unsigned g_dir[524288];
__device__ int      g_idx[32768];

// ---------- fp16 split helpers ----------
__device__ __forceinline__ void split1(float v, ushort_t& h, ushort_t& l) {
    __half hh = __float2half_rn(v);
    __half ll = __float2half_rn(v - __half2float(hh));
    h = __half_as_ushort(hh); l = __half_as_ushort(ll);
}
__device__ __forceinline__ void wsplit2(ushort_t* Ph, ushort_t* Pl, size_t off,
                                        float v0, float v1) {
    ushort_t h0, l0, h1, l1;
    split1(v0, h0, l0); split1(v1, h1, l1);
    *(unsigned*)&Ph[off] = (unsigned)h0 | ((unsigned)h1 << 16);
    *(unsigned*)&Pl[off] = (unsigned)l0 | ((unsigned)l1 << 16);
}

// ---------- core mma ----------
__device__ __forceinline__ void mma16(float c[4], const unsigned a[4], const unsigned b[2]) {
    asm volatile(
        "mma.sync.aligned.m16n8k16.row.col.f32.f16.f16.f32 "
        "{%0,%1,%2,%3},{%4,%5,%6,%7},{%8,%9},{%0,%1,%2,%3};\n"
        : "+f"(c[0]), "+f"(c[1]), "+f"(c[2]), "+f"(c[3])
        : "r"(a[0]), "r"(a[1]), "r"(a[2]), "r"(a[3]), "r"(b[0]), "r"(b[1]));
}

// As: [128 rows][12 uints] (8 used = 16 halves). Bs: [8 kpairs][136 uints] (128 used).
__device__ __forceinline__ void mma_tile16(const unsigned* AsH, const unsigned* AsL,
                                           const unsigned* BsH, const unsigned* BsL,
                                           int wm, int wn, int g, int tig,
                                           float (*acc)[4]) {
    unsigned aH[2][4], aL[2][4];
#pragma unroll
    for (int i = 0; i < 2; ++i) {
        int r = (wm * 32 + i * 16 + g) * 12 + tig;
        aH[i][0] = AsH[r]; aH[i][1] = AsH[r + 96]; aH[i][2] = AsH[r + 4]; aH[i][3] = AsH[r + 100];
        aL[i][0] = AsL[r]; aL[i][1] = AsL[r + 96]; aL[i][2] = AsL[r + 4]; aL[i][3] = AsL[r + 100];
    }
#pragma unroll
    for (int j = 0; j < 8; ++j) {
        int nb = wn * 64 + j * 8 + g;
        unsigned bH[2] = {BsH[tig * 136 + nb], BsH[(tig + 4) * 136 + nb]};
        unsigned bL[2] = {BsL[tig * 136 + nb], BsL[(tig + 4) * 136 + nb]};
#pragma unroll
        for (int i = 0; i < 2; ++i) {
            mma16(acc[i * 8 + j], aH[i], bH);
            mma16(acc[i * 8 + j], aL[i], bH);
            mma16(acc[i * 8 + j], aH[i], bL);
        }
    }
}

// ================= GEMM kernels =================

// C[16384,256] = A(planes)[16384,256] @ Wpk[128kp,256] + bias; optional fp32/plane outs
__global__ void __launch_bounds__(256, 2)
k_gemm_bias(const ushort_t* __restrict__ Ah, const ushort_t* __restrict__ Al,
            const unsigned* __restrict__ Bph, const unsigned* __restrict__ Bpl,
            const float* __restrict__ bias, float* __restrict__ Cf,
            ushort_t* __restrict__ Ch, ushort_t* __restrict__ Cl) {
    __shared__ unsigned AsH[1536], AsL[1536], BsH[1088], BsL[1088];
    int tid = threadIdx.x, w = tid >> 5, lane = tid & 31;
    int wm = w & 3, wn = w >> 2, g = lane >> 2, tig = lane & 3;
    int n0 = blockIdx.x * 128, m0 = blockIdx.y * 128;
    int arow = tid >> 1, apart = tid & 1;
    int bp = tid >> 5, bc = lane * 4;
    float acc[16][4] = {};
    for (int k0 = 0; k0 < 256; k0 += 16) {
        size_t aoff = (size_t)(m0 + arow) * 256 + k0 + apart * 8;
        uint4 ah = *(const uint4*)(Ah + aoff);
        uint4 al = *(const uint4*)(Al + aoff);
        size_t boff = (size_t)(k0 / 2 + bp) * 256 + n0 + bc;
        uint4 bh = *(const uint4*)(Bph + boff);
        uint4 bl = *(const uint4*)(Bpl + boff);
        __syncthreads();
        *(uint4*)&AsH[arow * 12 + apart * 4] = ah;
        *(uint4*)&AsL[arow * 12 + apart * 4] = al;
        *(uint4*)&BsH[bp * 136 + bc] = bh;
        *(uint4*)&BsL[bp * 136 + bc] = bl;
        __syncthreads();
        mma_tile16(AsH, AsL, BsH, BsL, wm, wn, g, tig, acc);
    }
#pragma unroll
    for (int i = 0; i < 2; ++i)
#pragma unroll
        for (int j = 0; j < 8; ++j) {
            int m = m0 + wm * 32 + i * 16 + g;
            int n = n0 + wn * 64 + j * 8 + 2 * tig;
            float b0 = bias[n], b1 = bias[n + 1];
            float* a = acc[i * 8 + j];
            float v0 = a[0] + b0, v1 = a[1] + b1, v2 = a[2] + b0, v3 = a[3] + b1;
            if (Cf) {
                *(float2*)&Cf[(size_t)m * 256 + n] = make_float2(v0, v1);
                *(float2*)&Cf[(size_t)(m + 8) * 256 + n] = make_float2(v2, v3);
            }
            if (Ch) {
                wsplit2(Ch, Cl, (size_t)m * 256 + n, v0, v1);
                wsplit2(Ch, Cl, (size_t)(m + 8) * 256 + n, v2, v3);
            }
        }
}

// scores: S[bh,q,k] = scale*Q.K^T + key mask
__global__ void __launch_bounds__(256, 2)
k_scores(const ushort_t* __restrict__ Qh, const ushort_t* __restrict__ Ql,
         const ushort_t* __restrict__ Kh, const ushort_t* __restrict__ Kl,
         float* __restrict__ S, const int* __restrict__ srcL) {
    __shared__ unsigned AsH[1536], AsL[1536], BsH[1088], BsL[1088];
    int tid = threadIdx.x, w = tid >> 5, lane = tid & 31;
    int wm = w & 3, wn = w >> 2, g = lane >> 2, tig = lane & 3;
    int n0 = blockIdx.x * 128, m0 = blockIdx.y * 128, bh = blockIdx.z;
    int b = bh >> 1, h = bh & 1;
    int arow = tid >> 1, apart = tid & 1;
    int btn = tid & 127, bpb = (tid >> 7) * 4;
    float acc[16][4] = {};
    for (int k0 = 0; k0 < 128; k0 += 16) {
        size_t aoff = (size_t)(b * 512 + m0 + arow) * 256 + h * 128 + k0 + apart * 8;
        uint4 ah = *(const uint4*)(Qh + aoff);
        uint4 al = *(const uint4*)(Ql + aoff);
        size_t koff = (size_t)(b * 512 + n0 + btn) * 256 + h * 128 + k0 + bpb * 2;
        uint4 bh4 = *(const uint4*)(Kh + koff);
        uint4 bl4 = *(const uint4*)(Kl + koff);
        __syncthreads();
        *(uint4*)&AsH[arow * 12 + apart * 4] = ah;
        *(uint4*)&AsL[arow * 12 + apart * 4] = al;
        BsH[(bpb + 0) * 136 + btn] = bh4.x; BsH[(bpb + 1) * 136 + btn] = bh4.y;
        BsH[(bpb + 2) * 136 + btn] = bh4.z; BsH[(bpb + 3) * 136 + btn] = bh4.w;
        BsL[(bpb + 0) * 136 + btn] = bl4.x; BsL[(bpb + 1) * 136 + btn] = bl4.y;
        BsL[(bpb + 2) * 136 + btn] = bl4.z; BsL[(bpb + 3) * 136 + btn] = bl4.w;
        __syncthreads();
        mma_tile16(AsH, AsL, BsH, BsL, wm, wn, g, tig, acc);
    }
    int sl = srcL[b];
    const float scale = 0.08838834764831845f;
#pragma unroll
    for (int i = 0; i < 2; ++i)
#pragma unroll
        for (int j = 0; j < 8; ++j) {
            int m = m0 + wm * 32 + i * 16 + g;
            int n = n0 + wn * 64 + j * 8 + 2 * tig;
            float* a = acc[i * 8 + j];
            bool p0 = (n >= sl), p1 = (n + 1 >= sl);
            float2 r0 = {p0 ? NEGF : a[0] * scale, p1 ? NEGF : a[1] * scale};
            float2 r1 = {p0 ? NEGF : a[2] * scale, p1 ? NEGF : a[3] * scale};
            *(float2*)&S[((size_t)bh * 512 + m) * 512 + n] = r0;
            *(float2*)&S[((size_t)bh * 512 + m + 8) * 512 + n] = r1;
        }
}

// attn out: O = softmax(S) @ V   (A = S planes, B = V planes paired on the fly)
__global__ void __launch_bounds__(256, 2)
k_attnout(const ushort_t* __restrict__ Sh, const ushort_t* __restrict__ Sl,
          const ushort_t* __restrict__ Vh, const ushort_t* __restrict__ Vl,
          ushort_t* __restrict__ Oh, ushort_t* __restrict__ Ol) {
    __shared__ unsigned AsH[1536], AsL[1536], BsH[1088], BsL[1088];
    int tid = threadIdx.x, w = tid >> 5, lane = tid & 31;
    int wm = w & 3, wn = w >> 2, g = lane >> 2, tig = lane & 3;
    int m0 = blockIdx.y * 128, bh = blockIdx.z;
    int b = bh >> 1, h = bh & 1;
    int arow = tid >> 1, apart = tid & 1;
    int bp = tid >> 5, bc = lane * 4;
    float acc[16][4] = {};
    for (int k0 = 0; k0 < 512; k0 += 16) {
        size_t aoff = ((size_t)bh * 512 + m0 + arow) * 512 + k0 + apart * 8;
        uint4 ah = *(const uint4*)(Sh + aoff);
        uint4 al = *(const uint4*)(Sl + aoff);
        const ushort_t* r0h = Vh + (size_t)(b * 512 + k0 + 2 * bp) * 256 + h * 128 + bc;
        uint2 uah = *(const uint2*)r0h, ubh = *(const uint2*)(r0h + 256);
        const ushort_t* r0l = Vl + (size_t)(b * 512 + k0 + 2 * bp) * 256 + h * 128 + bc;
        uint2 ual = *(const uint2*)r0l, ubl = *(const uint2*)(r0l + 256);
        __syncthreads();
        *(uint4*)&AsH[arow * 12 + apart * 4] = ah;
        *(uint4*)&AsL[arow * 12 + apart * 4] = al;
        BsH[bp * 136 + bc + 0] = (uah.x & 0xFFFFu) | (ubh.x << 16);
        BsH[bp * 136 + bc + 1] = (uah.x >> 16) | (ubh.x & 0xFFFF0000u);
        BsH[bp * 136 + bc + 2] = (uah.y & 0xFFFFu) | (ubh.y << 16);
        BsH[bp * 136 + bc + 3] = (uah.y >> 16) | (ubh.y & 0xFFFF0000u);
        BsL[bp * 136 + bc + 0] = (ual.x & 0xFFFFu) | (ubl.x << 16);
        BsL[bp * 136 + bc + 1] = (ual.x >> 16) | (ubl.x & 0xFFFF0000u);
        BsL[bp * 136 + bc + 2] = (ual.y & 0xFFFFu) | (ubl.y << 16);
        BsL[bp * 136 + bc + 3] = (ual.y >> 16) | (ubl.y & 0xFFFF0000u);
        __syncthreads();
        mma_tile16(AsH, AsL, BsH, BsL, wm, wn, g, tig, acc);
    }
#pragma unroll
    for (int i = 0; i < 2; ++i)
#pragma unroll
        for (int j = 0; j < 8; ++j) {
            int m = m0 + wm * 32 + i * 16 + g;
            int n = h * 128 + wn * 64 + j * 8 + 2 * tig;
            float* a = acc[i * 8 + j];
            wsplit2(Oh, Ol, (size_t)(b * 512 + m) * 256 + n, a[0], a[1]);
            wsplit2(Oh, Ol, (size_t)(b * 512 + m + 8) * 256 + n, a[2], a[3]);
        }
}

// conv1: H = relu(im2col(X) @ W1 + b1) -> H planes [16384,1024]; pipelined
__global__ void __launch_bounds__(256, 2)
k_conv1(const ushort_t* __restrict__ Ah, const ushort_t* __restrict__ Al,
        const unsigned* __restrict__ Bph, const unsigned* __restrict__ Bpl,
        const float* __restrict__ bias, ushort_t* __restrict__ Hh, ushort_t* __restrict__ Hl) {
    __shared__ unsigned AsH[2][1536], AsL[2][1536], BsH[2][1088], BsL[2][1088];
    int tid = threadIdx.x, w = tid >> 5, lane = tid & 31;
    int wm = w & 3, wn = w >> 2, g = lane >> 2, tig = lane & 3;
    int n0 = blockIdx.x * 128, m0 = blockIdx.y * 128;
    int bbase = m0 & ~511, tbase = m0 & 511;
    int arow = tid >> 1, apart = tid & 1;
    int bp = tid >> 5, bc = lane * 4;
    float acc[16][4] = {};
    const int NIT = 144;
    uint4 rah, ral, rbh, rbl;
    {
        int t = tbase + arow - 4;
        bool ok = ((unsigned)t < 512u);
        size_t aoff = ((size_t)(bbase + t)) * 256 + apart * 8;
        rah = ok ? *(const uint4*)(Ah + aoff) : make_uint4(0, 0, 0, 0);
        ral = ok ? *(const uint4*)(Al + aoff) : make_uint4(0, 0, 0, 0);
        size_t boff = (size_t)bp * 1024 + n0 + bc;
        rbh = *(const uint4*)(Bph + boff);
        rbl = *(const uint4*)(Bpl + boff);
        *(uint4*)&AsH[0][arow * 12 + apart * 4] = rah;
        *(uint4*)&AsL[0][arow * 12 + apart * 4] = ral;
        *(uint4*)&BsH[0][bp * 136 + bc] = rbh;
        *(uint4*)&BsL[0][bp * 136 + bc] = rbl;
    }
    __syncthreads();
    for (int it = 0; it < NIT; ++it) {
        int cur = it & 1;
        bool more = (it + 1 < NIT);
        if (more) {
            int nit = it + 1;
            int dk = nit >> 4, kk = (nit & 15) * 16;
            int t = tbase + arow + dk - 4;
            bool ok = ((unsigned)t < 512u);
            size_t aoff = ((size_t)(bbase + t)) * 256 + kk + apart * 8;
            rah = ok ? *(const uint4*)(Ah + aoff) : make_uint4(0, 0, 0, 0);
            ral = ok ? *(const uint4*)(Al + aoff) : make_uint4(0, 0, 0, 0);
            size_t boff = (size_t)(dk * 128 + kk / 2 + bp) * 1024 + n0 + bc;
            rbh = *(const uint4*)(Bph + boff);
            rbl = *(const uint4*)(Bpl + boff);
        }
        mma_tile16(AsH[cur], AsL[cur], BsH[cur], BsL[cur], wm, wn, g, tig, acc);
        if (more) {
            int nxt = cur ^ 1;
            *(uint4*)&AsH[nxt][arow * 12 + apart * 4] = rah;
            *(uint4*)&AsL[nxt][arow * 12 + apart * 4] = ral;
            *(uint4*)&BsH[nxt][bp * 136 + bc] = rbh;
            *(uint4*)&BsL[nxt][bp * 136 + bc] = rbl;
        }
        __syncthreads();
    }
#pragma unroll
    for (int i = 0; i < 2; ++i)
#pragma unroll
        for (int j = 0; j < 8; ++j) {
            int m = m0 + wm * 32 + i * 16 + g;
            int n = n0 + wn * 64 + j * 8 + 2 * tig;
            float b0 = bias[n], b1 = bias[n + 1];
            float* a = acc[i * 8 + j];
            wsplit2(Hh, Hl, (size_t)m * 1024 + n, fmaxf(a[0] + b0, 0.f), fmaxf(a[1] + b1, 0.f));
            wsplit2(Hh, Hl, (size_t)(m + 8) * 1024 + n, fmaxf(a[2] + b0, 0.f), fmaxf(a[3] + b1, 0.f));
        }
}

// conv2: T = im2col(H) @ W2 + b2 -> fp32 [16384,256]; pipelined
__global__ void __launch_bounds__(256, 2)
k_conv2(const ushort_t* __restrict__ Ah, const ushort_t* __restrict__ Al,
        const unsigned* __restrict__ Bph, const unsigned* __restrict__ Bpl,
        const float* __restrict__ bias, float* __restrict__ T) {
    __shared__ unsigned AsH[2][1536], AsL[2][1536], BsH[2][1088], BsL[2][1088];
    int tid = threadIdx.x, w = tid >> 5, lane = tid & 31;
    int wm = w & 3, wn = w >> 2, g = lane >> 2, tig = lane & 3;
    int n0 = blockIdx.x * 128, m0 = blockIdx.y * 128;
    int bbase = m0 & ~511, tbase = m0 & 511;
    int arow = tid >> 1, apart = tid & 1;
    int bp = tid >> 5, bc = lane * 4;
    float acc[16][4] = {};
    const int NIT = 576;
    uint4 rah, ral, rbh, rbl;
    {
        int t = tbase + arow - 4;
        bool ok = ((unsigned)t < 512u);
        size_t aoff = ((size_t)(bbase + t)) * 1024 + apart * 8;
        rah = ok ? *(const uint4*)(Ah + aoff) : make_uint4(0, 0, 0, 0);
        ral = ok ? *(const uint4*)(Al + aoff) : make_uint4(0, 0, 0, 0);
        size_t boff = (size_t)bp * 256 + n0 + bc;
        rbh = *(const uint4*)(Bph + boff);
        rbl = *(const uint4*)(Bpl + boff);
        *(uint4*)&AsH[0][arow * 12 + apart * 4] = rah;
        *(uint4*)&AsL[0][arow * 12 + apart * 4] = ral;
        *(uint4*)&BsH[0][bp * 136 + bc] = rbh;
        *(uint4*)&BsL[0][bp * 136 + bc] = rbl;
    }
    __syncthreads();
    for (int it = 0; it < NIT; ++it) {
        int cur = it & 1;
        bool more = (it + 1 < NIT);
        if (more) {
            int nit = it + 1;
            int dk = nit >> 6, kk = (nit & 63) * 16;
            int t = tbase + arow + dk - 4;
            bool ok = ((unsigned)t < 512u);
            size_t aoff = ((size_t)(bbase + t)) * 1024 + kk + apart * 8;
            rah = ok ? *(const uint4*)(Ah + aoff) : make_uint4(0, 0, 0, 0);
            ral = ok ? *(const uint4*)(Al + aoff) : make_uint4(0, 0, 0, 0);
            size_t boff = (size_t)(dk * 512 + kk / 2 + bp) * 256 + n0 + bc;
            rbh = *(const uint4*)(Bph + boff);
            rbl = *(const uint4*)(Bpl + boff);
        }
        mma_tile16(AsH[cur], AsL[cur], BsH[cur], BsL[cur], wm, wn, g, tig, acc);
        if (more) {
            int nxt = cur ^ 1;
            *(uint4*)&AsH[nxt][arow * 12 + apart * 4] = rah;
            *(uint4*)&AsL[nxt][arow * 12 + apart * 4] = ral;
            *(uint4*)&BsH[nxt][bp * 136 + bc] = rbh;
            *(uint4*)&BsL[nxt][bp * 136 + bc] = rbl;
        }
        __syncthreads();
    }
#pragma unroll
    for (int i = 0; i < 2; ++i)
#pragma unroll
        for (int j = 0; j < 8; ++j) {
            int m = m0 + wm * 32 + i * 16 + g;
            int n = n0 + wn * 64 + j * 8 + 2 * tig;
            float b0 = bias[n], b1 = bias[n + 1];
            float* a = acc[i * 8 + j];
            *(float2*)&T[(size_t)m * 256 + n] = make_float2(a[0] + b0, a[1] + b1);
            *(float2*)&T[(size_t)(m + 8) * 256 + n] = make_float2(a[2] + b0, a[3] + b1);
        }
}

// ================= producers / elementwise =================

__global__ void k_embed(const int* __restrict__ tok, const float* __restrict__ emb,
                        const float* __restrict__ pos, float* __restrict__ x,
                        ushort_t* __restrict__ xh, ushort_t* __restrict__ xl) {
    int row = blockIdx.x, d = threadIdx.x;
    int t = row & 511;
    int id = tok[row];
    size_t off = (size_t)row * 256 + d;
    float v = emb[(size_t)id * 256 + d] + pos[(size_t)t * 256 + d];
    x[off] = v;
    ushort_t h, l; split1(v, h, l);
    xh[off] = h; xl[off] = l;
}

__global__ void k_softmax(const float* __restrict__ S, ushort_t* __restrict__ Sh,
                          ushort_t* __restrict__ Sl) {
    __shared__ float red[4];
    size_t row = blockIdx.x;
    float4 v = ((const float4*)(S + row * 512))[threadIdx.x];
    int lane = threadIdx.x & 31, wid = threadIdx.x >> 5;
    float m = fmaxf(fmaxf(v.x, v.y), fmaxf(v.z, v.w));
#pragma unroll
    for (int o = 16; o > 0; o >>= 1) m = fmaxf(m, __shfl_xor_sync(~0u, m, o));
    if (lane == 0) red[wid] = m;
    __syncthreads();
    m = fmaxf(fmaxf(red[0], red[1]), fmaxf(red[2], red[3]));
    __syncthreads();
    v.x = expf(v.x - m); v.y = expf(v.y - m); v.z = expf(v.z - m); v.w = expf(v.w - m);
    float s = v.x + v.y + v.z + v.w;
#pragma unroll
    for (int o = 16; o > 0; o >>= 1) s += __shfl_xor_sync(~0u, s, o);
    if (lane == 0) red[wid] = s;
    __syncthreads();
    s = red[0] + red[1] + red[2] + red[3];
    float inv = 1.0f / s;
    size_t off = row * 512 + threadIdx.x * 4;
    wsplit2(Sh, Sl, off, v.x * inv, v.y * inv);
    wsplit2(Sh, Sl, off + 2, v.z * inv, v.w * inv);
}

__global__ void k_lnres(const float* __restrict__ t, const float* __restrict__ res,
                        const float* __restrict__ gam, const float* __restrict__ bet,
                        const int* __restrict__ srcL, float* __restrict__ out,
                        ushort_t* __restrict__ oh, ushort_t* __restrict__ ol) {
    __shared__ float red[8];
    int row = blockIdx.x, d = threadIdx.x;
    size_t off = (size_t)row * 256 + d;
    float val = t[off] + res[off];
    float s = val;
#pragma unroll
    for (int o = 16; o > 0; o >>= 1) s += __shfl_xor_sync(~0u, s, o);
    if ((d & 31) == 0) red[d >> 5] = s;
    __syncthreads();
    float tot = 0.f;
#pragma unroll
    for (int i = 0; i < 8; ++i) tot += red[i];
    float mean = tot * (1.0f / 256.0f);
    float dv = val - mean;
    __syncthreads();
    float s2 = dv * dv;
#pragma unroll
    for (int o = 16; o > 0; o >>= 1) s2 += __shfl_xor_sync(~0u, s2, o);
    if ((d & 31) == 0) red[d >> 5] = s2;
    __syncthreads();
    float tot2 = 0.f;
#pragma unroll
    for (int i = 0; i < 8; ++i) tot2 += red[i];
    float o = dv * rsqrtf(tot2 * (1.0f / 256.0f) + 1e-5f) * gam[d] + bet[d];
    if ((row & 511) >= srcL[row >> 9]) o = 0.f;
    out[off] = o;
    ushort_t h, l; split1(o, h, l);
    oh[off] = h; ol[off] = l;
}

// weight transpose: src[L][R][C][9] -> dst[L][9][C][R]  (fp32)
__global__ void k_wtrans(const float* __restrict__ src, float* __restrict__ dst, int R, int C) {
    __shared__ float s[32][33];
    int l = blockIdx.z;
    int CD = C * 9;
    int cd0 = blockIdx.x * 32, r0 = blockIdx.y * 32;
    const float* sp = src + (size_t)l * R * CD;
    float* dp = dst + (size_t)l * 9 * C * R;
    for (int i = threadIdx.y; i < 32; i += 8)
        s[i][threadIdx.x] = sp[(size_t)(r0 + i) * CD + cd0 + threadIdx.x];
    __syncthreads();
    for (int j = threadIdx.y; j < 32; j += 8) {
        int cd = cd0 + j;
        int c = cd / 9, dk = cd % 9;
        dp[((size_t)dk * C + c) * R + r0 + threadIdx.x] = s[threadIdx.x][j];
    }
}

// split + pair-pack: src fp32 [K][N] -> uint planes [K/2][N], N = 1<<nshift
__global__ void k_packsplit(const float* __restrict__ src, unsigned* __restrict__ Uh,
                            unsigned* __restrict__ Ul, int nshift) {
    size_t idx = (size_t)blockIdx.x * 256 + threadIdx.x;
    size_t kp = idx >> nshift;
    int n = (int)(idx & ((1u << nshift) - 1));
    size_t N = (size_t)1 << nshift;
    float a = src[(2 * kp) * N + n], b = src[(2 * kp + 1) * N + n];
    ushort_t ha, la, hb, lb;
    split1(a, ha, la); split1(b, hb, lb);
    Uh[idx] = (unsigned)ha | ((unsigned)hb << 16);
    Ul[idx] = (unsigned)la | ((unsigned)lb << 16);
}

// ================= MAS + expand =================

__global__ void k_vtrans(const float* __restrict__ val, float* __restrict__ vt,
                         const int* __restrict__ srcL, const int* __restrict__ melL) {
    __shared__ float s[32][33];
    int b = blockIdx.z;
    int x0 = blockIdx.x * 32, y0 = blockIdx.y * 32;
    int sl = srcL[b], ml = melL[b];
    const float* vp = val + (size_t)b * 512 * 1024;
    float* op = vt + (size_t)b * 1024 * 512;
    for (int i = threadIdx.y; i < 32; i += 8) {
        int x = x0 + i, y = y0 + threadIdx.x;
        float v = vp[(size_t)x * 1024 + y];
        s[i][threadIdx.x] = (x < sl && y < ml) ? v : 0.f;
    }
    __syncthreads();
    for (int j = threadIdx.y; j < 32; j += 8)
        op[(size_t)(y0 + j) * 512 + x0 + threadIdx.x] = s[threadIdx.x][j];
}

__global__ void k_masdp(const float* __restrict__ vt, const int* __restrict__ srcL,
                        const int* __restrict__ melL, unsigned* __restrict__ dir) {
    __shared__ float sv[512];
    int b = blockIdx.x, x = threadIdx.x;
    int sl = srcL[b], ml = melL[b];
    int lane = x & 31, wid = x >> 5;
    float v = 0.f;
    for (int j = 0; j < 1024; ++j) {
        sv[x] = v;
        __syncthreads();
        float v0 = x ? sv[x - 1] : NEGF;
        float val = vt[((size_t)b * 1024 + j) * 512 + x];
        bool d = (v >= v0);
        float vmax = d ? v : v0;
        float vnew = (x <= j) ? (vmax + val) : NEGF;
        bool dm = (x < sl && j < ml) ? d : true;
        unsigned bal = __ballot_sync(0xffffffffu, dm);
        if (lane == 0) dir[((size_t)b * 1024 + j) * 16 + wid] = bal;
        v = vnew;
        __syncthreads();
    }
}

__global__ void k_masbt(const unsigned* __restrict__ dir, const int* __restrict__ srcL,
                        int* __restrict__ idxout) {
    int b = threadIdx.x;
    if (b >= 32) return;
    int idx = srcL[b] - 1;
    for (int y = 1023; y >= 0; --y) {
        idxout[b * 1024 + y] = idx;
        unsigned w = dir[((size_t)b * 1024 + y) * 16 + (idx >> 5)];
        idx += (int)((w >> (idx & 31)) & 1u) - 1;
    }
}

__global__ void k_expand(const float* __restrict__ X, const int* __restrict__ idx,
                         const int* __restrict__ srcL, const int* __restrict__ melL,
                         float* __restrict__ out) {
    int row = blockIdx.x;
    int b = row >> 10, y = row & 1023;
    int d = threadIdx.x;
    float o = 0.f;
    if (y < melL[b]) {
        int ix = idx[row];
        if (ix >= 0 && ix < srcL[b])
            o = X[((size_t)(b << 9) + ix) * 256 + d];
    }
    out[(size_t)row * 256 + d] = o;
}

// ================= launch =================

extern "C" void kernel_launch(void* const* d_in, const int* in_sizes, int n_in,
                              void* d_out, int out_size) {
    const int* tokens = (const int*)d_in[0];
    const int* srcL   = (const int*)d_in[1];
    const int* melL   = (const int*)d_in[2];
    const float* value = (const float*)d_in[3];
    const float* embed = (const float*)d_in[4];
    const float* pos   = (const float*)d_in[5];
    const float* wq = (const float*)d_in[6];  const float* bq = (const float*)d_in[7];
    const float* wk = (const float*)d_in[8];  const float* bk = (const float*)d_in[9];
    const float* wv = (const float*)d_in[10]; const float* bv = (const float*)d_in[11];
    const float* wo = (const float*)d_in[12]; const float* bo = (const float*)d_in[13];
    const float* ln1g = (const float*)d_in[14]; const float* ln1b = (const float*)d_in[15];
    const float* c1w = (const float*)d_in[16]; const float* c1b = (const float*)d_in[17];
    const float* c2w = (const float*)d_in[18]; const float* c2b = (const float*)d_in[19];
    const float* ln2g = (const float*)d_in[20]; const float* ln2b = (const float*)d_in[21];
    float* out = (float*)d_out;

    float *px, *pt, *ps, *pvt, *pw1t, *pw2t;
    ushort_t *pxh, *pxl, *pqh, *pql, *pkh, *pkl, *pvh, *pvl, *poh, *pol;
    ushort_t *psh, *psl, *phh, *phl;
    unsigned *pw1h, *pw1l, *pw2h, *pw2l;
    unsigned *pwqh, *pwql, *pwkh, *pwkl, *pwvh, *pwvl, *pwoh, *pwol;
    unsigned* pdir; int* pidx;
    cudaGetSymbolAddress((void**)&px, g_x);   cudaGetSymbolAddress((void**)&pt, g_t);
    cudaGetSymbolAddress((void**)&ps, g_s);   cudaGetSymbolAddress((void**)&pvt, g_vt);
    cudaGetSymbolAddress((void**)&pw1t, g_w1t); cudaGetSymbolAddress((void**)&pw2t, g_w2t);
    cudaGetSymbolAddress((void**)&pxh, g_xh); cudaGetSymbolAddress((void**)&pxl, g_xl);
    cudaGetSymbolAddress((void**)&pqh, g_qh); cudaGetSymbolAddress((void**)&pql, g_ql);
    cudaGetSymbolAddress((void**)&pkh, g_kh); cudaGetSymbolAddress((void**)&pkl, g_kl);
    cudaGetSymbolAddress((void**)&pvh, g_vh); cudaGetSymbolAddress((void**)&pvl, g_vl);
    cudaGetSymbolAddress((void**)&poh, g_oh); cudaGetSymbolAddress((void**)&pol, g_ol);
    cudaGetSymbolAddress((void**)&psh, g_sh); cudaGetSymbolAddress((void**)&psl, g_sl);
    cudaGetSymbolAddress((void**)&phh, g_hh); cudaGetSymbolAddress((void**)&phl, g_hl);
    cudaGetSymbolAddress((void**)&pw1h, g_w1h); cudaGetSymbolAddress((void**)&pw1l, g_w1l);
    cudaGetSymbolAddress((void**)&pw2h, g_w2h); cudaGetSymbolAddress((void**)&pw2l, g_w2l);
    cudaGetSymbolAddress((void**)&pwqh, g_wqh); cudaGetSymbolAddress((void**)&pwql, g_wql);
    cudaGetSymbolAddress((void**)&pwkh, g_wkh); cudaGetSymbolAddress((void**)&pwkl, g_wkl);
    cudaGetSymbolAddress((void**)&pwvh, g_wvh); cudaGetSymbolAddress((void**)&pwvl, g_wvl);
    cudaGetSymbolAddress((void**)&pwoh, g_woh); cudaGetSymbolAddress((void**)&pwol, g_wol);
    cudaGetSymbolAddress((void**)&pdir, g_dir); cudaGetSymbolAddress((void**)&pidx, g_idx);

    dim3 blk256(256);
    // weight prep
    k_wtrans<<<dim3(72, 32, 4), dim3(32, 8)>>>(c1w, pw1t, 1024, 256);
    k_wtrans<<<dim3(288, 8, 4), dim3(32, 8)>>>(c2w, pw2t, 256, 1024);
    k_packsplit<<<18432, blk256>>>(pw1t, pw1h, pw1l, 10);
    k_packsplit<<<18432, blk256>>>(pw2t, pw2h, pw2l, 8);
    k_packsplit<<<512, blk256>>>(wq, pwqh, pwql, 8);
    k_packsplit<<<512, blk256>>>(wk, pwkh, pwkl, 8);
    k_packsplit<<<512, blk256>>>(wv, pwvh, pwvl, 8);
    k_packsplit<<<512, blk256>>>(wo, pwoh, pwol, 8);
    // inputs
    k_vtrans<<<dim3(16, 32, 32), dim3(32, 8)>>>(value, pvt, srcL, melL);
    k_embed<<<16384, blk256>>>(tokens, embed, pos, px, pxh, pxl);

    for (int l = 0; l < 4; ++l) {
        const unsigned *wqh_l = pwqh + l * 32768, *wql_l = pwql + l * 32768;
        const unsigned *wkh_l = pwkh + l * 32768, *wkl_l = pwkl + l * 32768;
        const unsigned *wvh_l = pwvh + l * 32768, *wvl_l = pwvl + l * 32768;
        const unsigned *woh_l = pwoh + l * 32768, *wol_l = pwol + l * 32768;

        k_gemm_bias<<<dim3(2, 128), blk256>>>(pxh, pxl, wqh_l, wql_l, bq + l * 256, nullptr, pqh, pql);
        k_gemm_bias<<<dim3(2, 128), blk256>>>(pxh, pxl, wkh_l, wkl_l, bk + l * 256, nullptr, pkh, pkl);
        k_gemm_bias<<<dim3(2, 128), blk256>>>(pxh, pxl, wvh_l, wvl_l, bv + l * 256, nullptr, pvh, pvl);
        k_scores<<<dim3(4, 4, 64), blk256>>>(pqh, pql, pkh, pkl, ps, srcL);
        k_softmax<<<32768, 128>>>(ps, psh, psl);
        k_attnout<<<dim3(1, 4, 64), blk256>>>(psh, psl, pvh, pvl, poh, pol);
        k_gemm_bias<<<dim3(2, 128), blk256>>>(poh, pol, woh_l, wol_l, bo + l * 256, pt, nullptr, nullptr);
        k_lnres<<<16384, blk256>>>(pt, px, ln1g + l * 256, ln1b + l * 256, srcL, px, pxh, pxl);

        k_conv1<<<dim3(8, 128), blk256>>>(pxh, pxl, pw1h + (size_t)l * 1179648,
                                          pw1l + (size_t)l * 1179648, c1b + l * 1024, phh, phl);
        k_conv2<<<dim3(2, 128), blk256>>>(phh, phl, pw2h + (size_t)l * 1179648,
                                          pw2l + (size_t)l * 1179648, c2b + l * 256, pt);
        k_lnres<<<16384, blk256>>>(pt, px, ln2g + l * 256, ln2b + l * 256, srcL, px, pxh, pxl);
    }

    k_masdp<<<32, 512>>>(pvt, srcL, melL, pdir);
    k_masbt<<<1, 32>>>(pdir, srcL, pidx);
    k_expand<<<32768, blk256>>>(px, pidx, srcL, melL, out);
}